// round 1
// baseline (speedup 1.0000x reference)
#include <cuda_runtime.h>
#include <math.h>

#define N_NODES 50000
#define HIDDEN  128
#define HEADS   8
#define NH      (N_NODES * HIDDEN)

// ---------------- scratch (device globals: allocation-free rule) ----------------
__device__ float g_deg_out[N_NODES];       // becomes norm_out after norm_kernel
__device__ float g_deg_in[N_NODES];        // becomes norm_in
__device__ float g_agg[NH];                // 25.6 MB
__device__ float g_QKV[3 * NH];            // 76.8 MB : Q | K | V
__device__ float g_z[N_NODES * HEADS];     // 1.6 MB

// vector atomic reduce (sm_90+): 1 instruction per 16B instead of 4 atomicAdds
__device__ __forceinline__ void red_add_v4(float* p, float4 v) {
    asm volatile("red.global.add.v4.f32 [%0], {%1, %2, %3, %4};"
                 :: "l"(p), "f"(v.x), "f"(v.y), "f"(v.z), "f"(v.w)
                 : "memory");
}

// ---------------- 0: zero all accumulators ----------------
__global__ void zero_kernel(float* __restrict__ out) {
    int i = blockIdx.x * blockDim.x + threadIdx.x;
    int stride = gridDim.x * blockDim.x;
    for (int j = i; j < NH; j += stride) { g_agg[j] = 0.f; out[j] = 0.f; }
    for (int j = i; j < N_NODES * HEADS; j += stride) g_z[j] = 0.f;
    for (int j = i; j < N_NODES; j += stride) { g_deg_out[j] = 0.f; g_deg_in[j] = 0.f; }
}

// ---------------- 1: degrees ----------------
__global__ void degree_kernel(const int* __restrict__ src, const int* __restrict__ dst, int E) {
    int e = blockIdx.x * blockDim.x + threadIdx.x;
    if (e < E) {
        atomicAdd(&g_deg_out[src[e]], 1.f);
        atomicAdd(&g_deg_in[dst[e]], 1.f);
    }
}

// ---------------- 2: norms = rsqrt(max(deg,1)) in place ----------------
__global__ void norm_kernel() {
    int i = blockIdx.x * blockDim.x + threadIdx.x;
    if (i < N_NODES) {
        g_deg_out[i] = rsqrtf(fmaxf(g_deg_out[i], 1.f));
        g_deg_in[i]  = rsqrtf(fmaxf(g_deg_in[i], 1.f));
    }
}

// ---------------- 3: aggregate: agg[dst] += h[src] * norm_out[src] ----------------
// one warp per edge; lane handles one float4 (4 of 128 feats)
__global__ void aggregate_kernel(const float* __restrict__ h,
                                 const int* __restrict__ src,
                                 const int* __restrict__ dst, int E) {
    int gw   = (blockIdx.x * blockDim.x + threadIdx.x) >> 5;
    int lane = threadIdx.x & 31;
    if (gw >= E) return;
    int s = __ldg(src + gw);
    int d = __ldg(dst + gw);
    float no = g_deg_out[s];
    const float4* h4 = (const float4*)h;
    float4 v = h4[(size_t)s * 32 + lane];
    v.x *= no; v.y *= no; v.z *= no; v.w *= no;
    red_add_v4(&g_agg[(size_t)d * 128 + (lane << 2)], v);
}

// ---------------- 4: QKV = relu((norm_in .* agg) @ W + b) ----------------
// BM=64 rows, BN=128 (one full weight matrix per blockIdx.y), BK=16.
// 256 threads, each computes 8 rows x 4 cols.
__global__ __launch_bounds__(256) void gemm_qkv(
    const float* __restrict__ Wq, const float* __restrict__ bq,
    const float* __restrict__ Wk, const float* __restrict__ bk,
    const float* __restrict__ Wv, const float* __restrict__ bv)
{
    const int mat = blockIdx.y;
    const float* W = (mat == 0) ? Wq : (mat == 1) ? Wk : Wv;
    const float* b = (mat == 0) ? bq : (mat == 1) ? bk : bv;
    float* out = g_QKV + (size_t)mat * NH;

    __shared__ float As[16][72];    // [k][m], padded stride 72: conflict-free stores
    __shared__ float Ws[16][128];   // [k][n]

    const int tid = threadIdx.x;
    const int tx = tid & 31;        // col group: c0 = tx*4
    const int ty = tid >> 5;        // row group: r0 = ty*8
    const int c0 = tx << 2;
    const int r0 = ty << 3;
    const int row0 = blockIdx.x * 64;

    // A-tile load mapping: thread -> (row, 4 k's)
    const int la_row = tid >> 2;          // 0..63
    const int la_k   = (tid & 3) << 2;    // 0,4,8,12
    const int arow = row0 + la_row;
    const float nin = (arow < N_NODES) ? g_deg_in[arow] : 0.f;

    float acc[8][4];
    #pragma unroll
    for (int i = 0; i < 8; i++)
        #pragma unroll
        for (int j = 0; j < 4; j++) acc[i][j] = 0.f;

    for (int k0 = 0; k0 < 128; k0 += 16) {
        float4 a = make_float4(0.f, 0.f, 0.f, 0.f);
        if (arow < N_NODES)
            a = *(const float4*)&g_agg[(size_t)arow * 128 + k0 + la_k];
        As[la_k + 0][la_row] = a.x * nin;
        As[la_k + 1][la_row] = a.y * nin;
        As[la_k + 2][la_row] = a.z * nin;
        As[la_k + 3][la_row] = a.w * nin;

        const float4* Wsrc = (const float4*)(W + k0 * 128);
        ((float4*)Ws)[tid]       = Wsrc[tid];
        ((float4*)Ws)[tid + 256] = Wsrc[tid + 256];
        __syncthreads();

        #pragma unroll
        for (int kk = 0; kk < 16; kk++) {
            float4 a0 = *(const float4*)&As[kk][r0];
            float4 a1 = *(const float4*)&As[kk][r0 + 4];
            float4 w  = *(const float4*)&Ws[kk][c0];
            float av[8] = {a0.x, a0.y, a0.z, a0.w, a1.x, a1.y, a1.z, a1.w};
            float wv[4] = {w.x, w.y, w.z, w.w};
            #pragma unroll
            for (int i = 0; i < 8; i++)
                #pragma unroll
                for (int j = 0; j < 4; j++)
                    acc[i][j] += av[i] * wv[j];
        }
        __syncthreads();
    }

    float4 bv4 = *(const float4*)&b[c0];
    #pragma unroll
    for (int i = 0; i < 8; i++) {
        int row = row0 + r0 + i;
        if (row < N_NODES) {
            float4 o;
            o.x = fmaxf(acc[i][0] + bv4.x, 0.f);
            o.y = fmaxf(acc[i][1] + bv4.y, 0.f);
            o.z = fmaxf(acc[i][2] + bv4.z, 0.f);
            o.w = fmaxf(acc[i][3] + bv4.w, 0.f);
            *(float4*)&out[(size_t)row * 128 + c0] = o;
        }
    }
}

// ---------------- 5: edge attention ----------------
// one warp per edge: score_h = <K[src],Q[dst]>_h ; p = exp(clip(score/4,-10,10))
// out[dst] += V[src]*p  (red.v4) ; z[dst,h] += p
__global__ void edge_attn(const int* __restrict__ src, const int* __restrict__ dst,
                          float* __restrict__ out, int E) {
    int gw   = (blockIdx.x * blockDim.x + threadIdx.x) >> 5;
    int lane = threadIdx.x & 31;
    if (gw >= E) return;
    int s = __ldg(src + gw);
    int d = __ldg(dst + gw);

    const float4* Q4 = (const float4*)g_QKV;
    const float4* K4 = (const float4*)(g_QKV + NH);
    const float4* V4 = (const float4*)(g_QKV + 2 * NH);

    float4 kk = K4[(size_t)s * 32 + lane];
    float4 qq = Q4[(size_t)d * 32 + lane];
    float p = kk.x * qq.x + kk.y * qq.y + kk.z * qq.z + kk.w * qq.w;
    // reduce within 4-lane head group (lanes 4h..4h+3)
    p += __shfl_xor_sync(0xffffffffu, p, 1);
    p += __shfl_xor_sync(0xffffffffu, p, 2);
    float sc = __expf(fminf(fmaxf(p * 0.25f, -10.f), 10.f));

    float4 v = V4[(size_t)s * 32 + lane];
    v.x *= sc; v.y *= sc; v.z *= sc; v.w *= sc;
    red_add_v4(out + (size_t)d * 128 + (lane << 2), v);
    if ((lane & 3) == 0)
        atomicAdd(&g_z[d * HEADS + (lane >> 2)], sc);
}

// ---------------- 6: out /= (z + 1e-6) ----------------
__global__ void finalize_kernel(float* __restrict__ out) {
    int i = blockIdx.x * blockDim.x + threadIdx.x;  // float4 index
    if (i < NH / 4) {
        int node = i >> 5;
        int head = (i & 31) >> 2;
        float inv = 1.f / (g_z[node * HEADS + head] + 1e-6f);
        float4 o = ((float4*)out)[i];
        o.x *= inv; o.y *= inv; o.z *= inv; o.w *= inv;
        ((float4*)out)[i] = o;
    }
}

// ---------------- launcher ----------------
extern "C" void kernel_launch(void* const* d_in, const int* in_sizes, int n_in,
                              void* d_out, int out_size) {
    const float* h  = (const float*)d_in[0];
    const float* Wq = (const float*)d_in[1];
    const float* bq = (const float*)d_in[2];
    const float* Wk = (const float*)d_in[3];
    const float* bk = (const float*)d_in[4];
    const float* Wv = (const float*)d_in[5];
    const float* bv = (const float*)d_in[6];
    const int*  src = (const int*)d_in[7];
    const int*  dst = (const int*)d_in[8];
    const int E = in_sizes[7];
    float* out = (float*)d_out;

    zero_kernel<<<4096, 256>>>(out);
    degree_kernel<<<(E + 255) / 256, 256>>>(src, dst, E);
    norm_kernel<<<(N_NODES + 255) / 256, 256>>>();

    long long ethreads = (long long)E * 32;
    int eblocks = (int)((ethreads + 255) / 256);
    aggregate_kernel<<<eblocks, 256>>>(h, src, dst, E);

    dim3 gg((N_NODES + 63) / 64, 3);
    gemm_qkv<<<gg, 256>>>(Wq, bq, Wk, bk, Wv, bv);

    edge_attn<<<eblocks, 256>>>(src, dst, out, E);
    finalize_kernel<<<(NH / 4 + 255) / 256, 256>>>(out);
}

// round 2
// speedup vs baseline: 1.6541x; 1.6541x over previous
#include <cuda_runtime.h>
#include <math.h>

#define N_NODES 50000
#define HIDDEN  128
#define HEADS   8
#define NH      (N_NODES * HIDDEN)
#define E_MAX   1600000

// ---------------- scratch (device globals: allocation-free rule) ----------------
__device__ int   g_cnt_out[N_NODES];        // out-degree (int)
__device__ int   g_cnt_in[N_NODES];         // in-degree (int)
__device__ int   g_rowptr[N_NODES + 1];     // CSR row offsets (by dst)
__device__ int   g_cur[N_NODES];            // bucket cursors
__device__ int   g_srt_src[E_MAX];          // src indices sorted by dst
__device__ float g_norm_out[N_NODES];
__device__ float g_norm_in[N_NODES];
__device__ float g_agg[NH];                 // 25.6 MB (includes norm_in factor)
__device__ float g_QKV[3 * NH];             // 76.8 MB : Q | K | V

// ---------------- 0: zero the degree counters ----------------
__global__ void zero_cnt() {
    int i = blockIdx.x * blockDim.x + threadIdx.x;
    if (i < N_NODES) { g_cnt_out[i] = 0; g_cnt_in[i] = 0; }
}

// ---------------- 1: degree histograms ----------------
__global__ void degree_kernel(const int* __restrict__ src, const int* __restrict__ dst, int E) {
    int e = blockIdx.x * blockDim.x + threadIdx.x;
    if (e < E) {
        atomicAdd(&g_cnt_out[src[e]], 1);
        atomicAdd(&g_cnt_in[dst[e]], 1);
    }
}

// ---------------- 2: single-block exclusive scan of in-degrees -> rowptr ----------------
__global__ void scan_kernel() {
    __shared__ int wsum[32];
    __shared__ int s_carry;
    const int tid = threadIdx.x, lane = tid & 31, wid = tid >> 5;
    if (tid == 0) { s_carry = 0; g_rowptr[0] = 0; }
    __syncthreads();
    for (int base = 0; base < N_NODES; base += 1024) {
        int i = base + tid;
        int v = (i < N_NODES) ? g_cnt_in[i] : 0;
        int x = v;
        #pragma unroll
        for (int o = 1; o < 32; o <<= 1) {
            int t = __shfl_up_sync(0xffffffffu, x, o);
            if (lane >= o) x += t;
        }
        if (lane == 31) wsum[wid] = x;
        __syncthreads();
        if (wid == 0) {
            int w = wsum[lane];
            #pragma unroll
            for (int o = 1; o < 32; o <<= 1) {
                int t = __shfl_up_sync(0xffffffffu, w, o);
                if (lane >= o) w += t;
            }
            wsum[lane] = w;
        }
        __syncthreads();
        int incl = x + (wid > 0 ? wsum[wid - 1] : 0) + s_carry;
        if (i < N_NODES) g_rowptr[i + 1] = incl;
        __syncthreads();
        if (tid == 1023) s_carry = incl;
        __syncthreads();
    }
}

// ---------------- 3: norms + cursor init ----------------
__global__ void norm_kernel() {
    int i = blockIdx.x * blockDim.x + threadIdx.x;
    if (i < N_NODES) {
        g_norm_out[i] = rsqrtf(fmaxf((float)g_cnt_out[i], 1.f));
        g_norm_in[i]  = rsqrtf(fmaxf((float)g_cnt_in[i], 1.f));
        g_cur[i]      = g_rowptr[i];
    }
}

// ---------------- 4: bucket fill (counting sort by dst) ----------------
__global__ void bucket_kernel(const int* __restrict__ src, const int* __restrict__ dst, int E) {
    int e = blockIdx.x * blockDim.x + threadIdx.x;
    if (e < E) {
        int p = atomicAdd(&g_cur[dst[e]], 1);
        g_srt_src[p] = src[e];
    }
}

// ---------------- 5: gather-aggregate: agg[d] = norm_in[d] * sum_{s in N(d)} h[s]*norm_out[s] ----------------
// one warp per node; lane handles one float4 of the 128 features
__global__ __launch_bounds__(256) void agg_gather(const float* __restrict__ h) {
    int node = (blockIdx.x * blockDim.x + threadIdx.x) >> 5;
    int lane = threadIdx.x & 31;
    if (node >= N_NODES) return;
    int beg = g_rowptr[node], end = g_rowptr[node + 1];
    const float4* h4 = (const float4*)h;
    float4 acc = make_float4(0.f, 0.f, 0.f, 0.f);
    int j = beg;
    for (; j + 4 <= end; j += 4) {
        int s0 = g_srt_src[j], s1 = g_srt_src[j + 1], s2 = g_srt_src[j + 2], s3 = g_srt_src[j + 3];
        float n0 = g_norm_out[s0], n1 = g_norm_out[s1], n2 = g_norm_out[s2], n3 = g_norm_out[s3];
        float4 a = h4[(size_t)s0 * 32 + lane];
        float4 b = h4[(size_t)s1 * 32 + lane];
        float4 c = h4[(size_t)s2 * 32 + lane];
        float4 d = h4[(size_t)s3 * 32 + lane];
        acc.x += a.x * n0 + b.x * n1 + c.x * n2 + d.x * n3;
        acc.y += a.y * n0 + b.y * n1 + c.y * n2 + d.y * n3;
        acc.z += a.z * n0 + b.z * n1 + c.z * n2 + d.z * n3;
        acc.w += a.w * n0 + b.w * n1 + c.w * n2 + d.w * n3;
    }
    for (; j < end; j++) {
        int s = g_srt_src[j];
        float n = g_norm_out[s];
        float4 a = h4[(size_t)s * 32 + lane];
        acc.x += a.x * n; acc.y += a.y * n; acc.z += a.z * n; acc.w += a.w * n;
    }
    float ni = g_norm_in[node];
    acc.x *= ni; acc.y *= ni; acc.z *= ni; acc.w *= ni;
    *(float4*)&g_agg[(size_t)node * 128 + (lane << 2)] = acc;
}

// ---------------- 6: QKV = relu(agg @ W + b) ----------------
// BM=64, BN=128 (one weight matrix per blockIdx.y), BK=16, 256 threads, 8x4 per thread
__global__ __launch_bounds__(256) void gemm_qkv(
    const float* __restrict__ Wq, const float* __restrict__ bq,
    const float* __restrict__ Wk, const float* __restrict__ bk,
    const float* __restrict__ Wv, const float* __restrict__ bv)
{
    const int mat = blockIdx.y;
    const float* W = (mat == 0) ? Wq : (mat == 1) ? Wk : Wv;
    const float* b = (mat == 0) ? bq : (mat == 1) ? bk : bv;
    float* out = g_QKV + (size_t)mat * NH;

    __shared__ float As[16][72];
    __shared__ float Ws[16][128];

    const int tid = threadIdx.x;
    const int c0 = (tid & 31) << 2;
    const int r0 = (tid >> 5) << 3;
    const int row0 = blockIdx.x * 64;

    const int la_row = tid >> 2;
    const int la_k   = (tid & 3) << 2;
    const int arow = row0 + la_row;

    float acc[8][4];
    #pragma unroll
    for (int i = 0; i < 8; i++)
        #pragma unroll
        for (int j = 0; j < 4; j++) acc[i][j] = 0.f;

    for (int k0 = 0; k0 < 128; k0 += 16) {
        float4 a = make_float4(0.f, 0.f, 0.f, 0.f);
        if (arow < N_NODES)
            a = *(const float4*)&g_agg[(size_t)arow * 128 + k0 + la_k];
        As[la_k + 0][la_row] = a.x;
        As[la_k + 1][la_row] = a.y;
        As[la_k + 2][la_row] = a.z;
        As[la_k + 3][la_row] = a.w;

        const float4* Wsrc = (const float4*)(W + k0 * 128);
        ((float4*)Ws)[tid]       = Wsrc[tid];
        ((float4*)Ws)[tid + 256] = Wsrc[tid + 256];
        __syncthreads();

        #pragma unroll
        for (int kk = 0; kk < 16; kk++) {
            float4 a0 = *(const float4*)&As[kk][r0];
            float4 a1 = *(const float4*)&As[kk][r0 + 4];
            float4 w  = *(const float4*)&Ws[kk][c0];
            float av[8] = {a0.x, a0.y, a0.z, a0.w, a1.x, a1.y, a1.z, a1.w};
            float wv[4] = {w.x, w.y, w.z, w.w};
            #pragma unroll
            for (int i = 0; i < 8; i++)
                #pragma unroll
                for (int j = 0; j < 4; j++)
                    acc[i][j] += av[i] * wv[j];
        }
        __syncthreads();
    }

    float4 bv4 = *(const float4*)&b[c0];
    #pragma unroll
    for (int i = 0; i < 8; i++) {
        int row = row0 + r0 + i;
        if (row < N_NODES) {
            float4 o;
            o.x = fmaxf(acc[i][0] + bv4.x, 0.f);
            o.y = fmaxf(acc[i][1] + bv4.y, 0.f);
            o.z = fmaxf(acc[i][2] + bv4.z, 0.f);
            o.w = fmaxf(acc[i][3] + bv4.w, 0.f);
            *(float4*)&out[(size_t)row * 128 + c0] = o;
        }
    }
}

// ---------------- 7: gather-attention + finalize ----------------
// one warp per dst node. Q[d] held in registers; loop over sorted in-edges.
__global__ __launch_bounds__(256) void attn_gather(float* __restrict__ out) {
    int node = (blockIdx.x * blockDim.x + threadIdx.x) >> 5;
    int lane = threadIdx.x & 31;
    if (node >= N_NODES) return;
    int beg = g_rowptr[node], end = g_rowptr[node + 1];

    const float4* Q4 = (const float4*)g_QKV;
    const float4* K4 = (const float4*)(g_QKV + NH);
    const float4* V4 = (const float4*)(g_QKV + 2 * NH);

    float4 q = Q4[(size_t)node * 32 + lane];
    float4 acc = make_float4(0.f, 0.f, 0.f, 0.f);
    float z = 0.f;

    int j = beg;
    for (; j + 2 <= end; j += 2) {
        int s0 = g_srt_src[j], s1 = g_srt_src[j + 1];
        float4 k0 = K4[(size_t)s0 * 32 + lane];
        float4 k1 = K4[(size_t)s1 * 32 + lane];
        float4 v0 = V4[(size_t)s0 * 32 + lane];
        float4 v1 = V4[(size_t)s1 * 32 + lane];

        float p0 = k0.x * q.x + k0.y * q.y + k0.z * q.z + k0.w * q.w;
        float p1 = k1.x * q.x + k1.y * q.y + k1.z * q.z + k1.w * q.w;
        p0 += __shfl_xor_sync(0xffffffffu, p0, 1);
        p1 += __shfl_xor_sync(0xffffffffu, p1, 1);
        p0 += __shfl_xor_sync(0xffffffffu, p0, 2);
        p1 += __shfl_xor_sync(0xffffffffu, p1, 2);
        float sc0 = __expf(fminf(fmaxf(p0 * 0.25f, -10.f), 10.f));
        float sc1 = __expf(fminf(fmaxf(p1 * 0.25f, -10.f), 10.f));

        acc.x += v0.x * sc0 + v1.x * sc1;
        acc.y += v0.y * sc0 + v1.y * sc1;
        acc.z += v0.z * sc0 + v1.z * sc1;
        acc.w += v0.w * sc0 + v1.w * sc1;
        z += sc0 + sc1;
    }
    for (; j < end; j++) {
        int s = g_srt_src[j];
        float4 k = K4[(size_t)s * 32 + lane];
        float4 v = V4[(size_t)s * 32 + lane];
        float p = k.x * q.x + k.y * q.y + k.z * q.z + k.w * q.w;
        p += __shfl_xor_sync(0xffffffffu, p, 1);
        p += __shfl_xor_sync(0xffffffffu, p, 2);
        float sc = __expf(fminf(fmaxf(p * 0.25f, -10.f), 10.f));
        acc.x += v.x * sc; acc.y += v.y * sc; acc.z += v.z * sc; acc.w += v.w * sc;
        z += sc;
    }

    float inv = 1.f / (z + 1e-6f);
    acc.x *= inv; acc.y *= inv; acc.z *= inv; acc.w *= inv;
    *(float4*)&out[(size_t)node * 128 + (lane << 2)] = acc;
}

// ---------------- launcher ----------------
extern "C" void kernel_launch(void* const* d_in, const int* in_sizes, int n_in,
                              void* d_out, int out_size) {
    const float* h  = (const float*)d_in[0];
    const float* Wq = (const float*)d_in[1];
    const float* bq = (const float*)d_in[2];
    const float* Wk = (const float*)d_in[3];
    const float* bk = (const float*)d_in[4];
    const float* Wv = (const float*)d_in[5];
    const float* bv = (const float*)d_in[6];
    const int*  src = (const int*)d_in[7];
    const int*  dst = (const int*)d_in[8];
    const int E = in_sizes[7];
    float* out = (float*)d_out;

    zero_cnt<<<(N_NODES + 255) / 256, 256>>>();
    degree_kernel<<<(E + 255) / 256, 256>>>(src, dst, E);
    scan_kernel<<<1, 1024>>>();
    norm_kernel<<<(N_NODES + 255) / 256, 256>>>();
    bucket_kernel<<<(E + 255) / 256, 256>>>(src, dst, E);

    int nwblocks = (N_NODES * 32 + 255) / 256;
    agg_gather<<<nwblocks, 256>>>(h);

    dim3 gg((N_NODES + 63) / 64, 3);
    gemm_qkv<<<gg, 256>>>(Wq, bq, Wk, bk, Wv, bv);

    attn_gather<<<nwblocks, 256>>>(out);
}

// round 5
// speedup vs baseline: 2.1923x; 1.3254x over previous
#include <cuda_runtime.h>
#include <cuda_bf16.h>
#include <math.h>

#define N_NODES 50000
#define HIDDEN  128
#define HEADS   8
#define NH      (N_NODES * HIDDEN)
#define E_MAX   1600000
#define NCHUNK  ((N_NODES + 1023) / 1024)   // 49

// ---------------- scratch (device globals: allocation-free rule) ----------------
__device__ int   g_cnt_out[N_NODES];
__device__ int   g_cnt_in[N_NODES];
__device__ int   g_rowptr[N_NODES + 1];
__device__ int   g_cur[N_NODES];
__device__ int   g_srt_src[E_MAX];
__device__ int   g_chunk[64];
__device__ int   g_chunkpref[64];
__device__ float g_norm_out[N_NODES];
__device__ float g_norm_in[N_NODES];
__device__ float g_agg[NH];                     // 25.6 MB (norm_in folded in)
__device__ float g_QKV[2 * NH];                 // Q | K  (fp32)
__device__ __nv_bfloat16 g_Vbf[NH];             // V in bf16 (12.8 MB)
__device__ __nv_bfloat16 g_Wt_hi[3][128 * 128]; // W^T split-bf16 high parts
__device__ __nv_bfloat16 g_Wt_lo[3][128 * 128]; // W^T split-bf16 low parts

// ---------------- 0: zero counters ----------------
__global__ void zero_cnt() {
    int i = blockIdx.x * blockDim.x + threadIdx.x;
    if (i < N_NODES) { g_cnt_out[i] = 0; g_cnt_in[i] = 0; }
}

// ---------------- 1: degree histograms ----------------
__global__ void degree_kernel(const int* __restrict__ src, const int* __restrict__ dst, int E) {
    int e = blockIdx.x * blockDim.x + threadIdx.x;
    if (e < E) {
        atomicAdd(&g_cnt_out[src[e]], 1);
        atomicAdd(&g_cnt_in[dst[e]], 1);
    }
}

// ---------------- 2a: per-1024-chunk inclusive scan ----------------
__global__ void scan_local() {
    __shared__ int wsum[32];
    const int tid = threadIdx.x, lane = tid & 31, wid = tid >> 5;
    int i = blockIdx.x * 1024 + tid;
    int x = (i < N_NODES) ? g_cnt_in[i] : 0;
    #pragma unroll
    for (int o = 1; o < 32; o <<= 1) {
        int t = __shfl_up_sync(0xffffffffu, x, o);
        if (lane >= o) x += t;
    }
    if (lane == 31) wsum[wid] = x;
    __syncthreads();
    if (wid == 0) {
        int w = wsum[lane];
        #pragma unroll
        for (int o = 1; o < 32; o <<= 1) {
            int t = __shfl_up_sync(0xffffffffu, w, o);
            if (lane >= o) w += t;
        }
        wsum[lane] = w;
    }
    __syncthreads();
    int incl = x + (wid > 0 ? wsum[wid - 1] : 0);
    if (i < N_NODES) g_rowptr[i + 1] = incl;
    if (tid == 1023) g_chunk[blockIdx.x] = incl;
}

// ---------------- 2b: scan the chunk totals (64 threads, Hillis-Steele) ----------------
__global__ void scan_chunks() {
    __shared__ int s[64];
    int t = threadIdx.x;
    s[t] = (t < NCHUNK) ? g_chunk[t] : 0;
    __syncthreads();
    #pragma unroll
    for (int off = 1; off < 64; off <<= 1) {
        int v = (t >= off) ? s[t - off] : 0;
        __syncthreads();
        s[t] += v;
        __syncthreads();
    }
    if (t < NCHUNK) g_chunkpref[t] = (t > 0) ? s[t - 1] : 0;
}

// ---------------- 2c: finalize rowptr + cursors + norms ----------------
__global__ void finalize_csr() {
    int i = blockIdx.x * blockDim.x + threadIdx.x;
    if (i < N_NODES) {
        int inc = g_rowptr[i + 1] + g_chunkpref[i >> 10];
        g_rowptr[i + 1] = inc;
        int cin = g_cnt_in[i];
        g_cur[i] = inc - cin;
        g_norm_in[i]  = rsqrtf(fmaxf((float)cin, 1.f));
        g_norm_out[i] = rsqrtf(fmaxf((float)g_cnt_out[i], 1.f));
        if (i == 0) g_rowptr[0] = 0;
    }
}

// ---------------- 3: counting-sort bucket fill ----------------
__global__ void bucket_kernel(const int* __restrict__ src, const int* __restrict__ dst, int E) {
    int e = blockIdx.x * blockDim.x + threadIdx.x;
    if (e < E) {
        int p = atomicAdd(&g_cur[dst[e]], 1);
        g_srt_src[p] = src[e];
    }
}

// ---------------- 4: W -> transposed split-bf16 (once per launch) ----------------
__global__ void prep_w(const float* __restrict__ Wq, const float* __restrict__ Wk,
                       const float* __restrict__ Wv) {
    int t = blockIdx.x * 256 + threadIdx.x;
    if (t >= 3 * 128 * 128) return;
    int mat = t >> 14, rem = t & 16383;
    int n = rem >> 7, k = rem & 127;
    const float* W = (mat == 0) ? Wq : (mat == 1) ? Wk : Wv;
    float x = W[k * 128 + n];
    __nv_bfloat16 h = __float2bfloat16(x);
    g_Wt_hi[mat][n * 128 + k] = h;
    g_Wt_lo[mat][n * 128 + k] = __float2bfloat16(x - __bfloat162float(h));
}

// ---------------- 5: gather-aggregate ----------------
__global__ __launch_bounds__(256) void agg_gather(const float* __restrict__ h) {
    int node = (blockIdx.x * blockDim.x + threadIdx.x) >> 5;
    int lane = threadIdx.x & 31;
    if (node >= N_NODES) return;
    int beg = g_rowptr[node], end = g_rowptr[node + 1];
    const float4* h4 = (const float4*)h;
    float4 acc = make_float4(0.f, 0.f, 0.f, 0.f);
    int j = beg;
    for (; j + 4 <= end; j += 4) {
        int s0 = g_srt_src[j], s1 = g_srt_src[j + 1], s2 = g_srt_src[j + 2], s3 = g_srt_src[j + 3];
        float n0 = g_norm_out[s0], n1 = g_norm_out[s1], n2 = g_norm_out[s2], n3 = g_norm_out[s3];
        float4 a = h4[(size_t)s0 * 32 + lane];
        float4 b = h4[(size_t)s1 * 32 + lane];
        float4 c = h4[(size_t)s2 * 32 + lane];
        float4 d = h4[(size_t)s3 * 32 + lane];
        acc.x += a.x * n0 + b.x * n1 + c.x * n2 + d.x * n3;
        acc.y += a.y * n0 + b.y * n1 + c.y * n2 + d.y * n3;
        acc.z += a.z * n0 + b.z * n1 + c.z * n2 + d.z * n3;
        acc.w += a.w * n0 + b.w * n1 + c.w * n2 + d.w * n3;
    }
    for (; j < end; j++) {
        int s = g_srt_src[j];
        float n = g_norm_out[s];
        float4 a = h4[(size_t)s * 32 + lane];
        acc.x += a.x * n; acc.y += a.y * n; acc.z += a.z * n; acc.w += a.w * n;
    }
    float ni = g_norm_in[node];
    acc.x *= ni; acc.y *= ni; acc.z *= ni; acc.w *= ni;
    *(float4*)&g_agg[(size_t)node * 128 + (lane << 2)] = acc;
}

// ---------------- 6: QKV GEMM via split-bf16 tensor cores ----------------
__device__ __forceinline__ void mma16816(float* c, const unsigned* a, unsigned b0, unsigned b1) {
    asm volatile(
        "mma.sync.aligned.m16n8k16.row.col.f32.bf16.bf16.f32 "
        "{%0,%1,%2,%3}, {%4,%5,%6,%7}, {%8,%9}, {%0,%1,%2,%3};\n"
        : "+f"(c[0]), "+f"(c[1]), "+f"(c[2]), "+f"(c[3])
        : "r"(a[0]), "r"(a[1]), "r"(a[2]), "r"(a[3]), "r"(b0), "r"(b1));
}

// M-tile 128 x N 128, K streamed in 32-chunks. 8 warps, warp w owns rows [16w,16w+16).
__global__ __launch_bounds__(256, 2) void gemm_qkv_mma(
    const float* __restrict__ bq, const float* __restrict__ bk, const float* __restrict__ bv)
{
    const int mat = blockIdx.y;
    const float* bias = (mat == 0) ? bq : (mat == 1) ? bk : bv;
    const __nv_bfloat16* WtH = g_Wt_hi[mat];
    const __nv_bfloat16* WtL = g_Wt_lo[mat];

    // stride 40 bf16 (20 words): conflict-free frag loads
    __shared__ __nv_bfloat16 sA_hi[128 * 40];
    __shared__ __nv_bfloat16 sA_lo[128 * 40];
    __shared__ __nv_bfloat16 sB_hi[128 * 40];
    __shared__ __nv_bfloat16 sB_lo[128 * 40];

    const int tid = threadIdx.x;
    const int warp = tid >> 5, lane = tid & 31;
    const int g = lane >> 2, tg = lane & 3;
    const int row0 = blockIdx.x * 128;

    float acc[16][4];
    #pragma unroll
    for (int i = 0; i < 16; i++)
        #pragma unroll
        for (int j = 0; j < 4; j++) acc[i][j] = 0.f;

    const int r = tid >> 1;           // 0..127 (A row / B n-row)
    const int hh = tid & 1;           // half: 16 elems each

    for (int k0 = 0; k0 < 128; k0 += 32) {
        // --- load + split A tile [128 rows x 32 k] ---
        float xs[16];
        int arow = row0 + r;
        if (arow < N_NODES) {
            const float4* p = (const float4*)(g_agg + (size_t)arow * 128 + k0 + hh * 16);
            float4 a = p[0], b = p[1], c = p[2], d = p[3];
            xs[0]=a.x; xs[1]=a.y; xs[2]=a.z; xs[3]=a.w;
            xs[4]=b.x; xs[5]=b.y; xs[6]=b.z; xs[7]=b.w;
            xs[8]=c.x; xs[9]=c.y; xs[10]=c.z; xs[11]=c.w;
            xs[12]=d.x; xs[13]=d.y; xs[14]=d.z; xs[15]=d.w;
        } else {
            #pragma unroll
            for (int i = 0; i < 16; i++) xs[i] = 0.f;
        }
        __align__(16) __nv_bfloat16 hi[16], lo[16];
        #pragma unroll
        for (int i = 0; i < 16; i++) {
            hi[i] = __float2bfloat16(xs[i]);
            lo[i] = __float2bfloat16(xs[i] - __bfloat162float(hi[i]));
        }
        *(int4*)&sA_hi[r * 40 + hh * 16]     = ((int4*)hi)[0];
        *(int4*)&sA_hi[r * 40 + hh * 16 + 8] = ((int4*)hi)[1];
        *(int4*)&sA_lo[r * 40 + hh * 16]     = ((int4*)lo)[0];
        *(int4*)&sA_lo[r * 40 + hh * 16 + 8] = ((int4*)lo)[1];

        // --- load pre-split Wt tile [128 n x 32 k] ---
        const int4* srcH = (const int4*)(WtH + r * 128 + k0 + hh * 16);
        const int4* srcL = (const int4*)(WtL + r * 128 + k0 + hh * 16);
        *(int4*)&sB_hi[r * 40 + hh * 16]     = srcH[0];
        *(int4*)&sB_hi[r * 40 + hh * 16 + 8] = srcH[1];
        *(int4*)&sB_lo[r * 40 + hh * 16]     = srcL[0];
        *(int4*)&sB_lo[r * 40 + hh * 16 + 8] = srcL[1];
        __syncthreads();

        const unsigned* pAH = (const unsigned*)sA_hi;
        const unsigned* pAL = (const unsigned*)sA_lo;
        const unsigned* pBH = (const unsigned*)sB_hi;
        const unsigned* pBL = (const unsigned*)sB_lo;
        const int ra = warp * 16 + g;

        #pragma unroll
        for (int kw = 0; kw <= 8; kw += 8) {   // two k16 sub-steps (word offset 0, 8)
            unsigned aH[4], aL[4];
            aH[0] = pAH[ra * 20 + kw + tg];
            aH[1] = pAH[(ra + 8) * 20 + kw + tg];
            aH[2] = pAH[ra * 20 + kw + tg + 4];
            aH[3] = pAH[(ra + 8) * 20 + kw + tg + 4];
            aL[0] = pAL[ra * 20 + kw + tg];
            aL[1] = pAL[(ra + 8) * 20 + kw + tg];
            aL[2] = pAL[ra * 20 + kw + tg + 4];
            aL[3] = pAL[(ra + 8) * 20 + kw + tg + 4];
            #pragma unroll
            for (int nt = 0; nt < 16; nt++) {
                int nb = nt * 8 + g;
                unsigned bH0 = pBH[nb * 20 + kw + tg];
                unsigned bH1 = pBH[nb * 20 + kw + tg + 4];
                unsigned bL0 = pBL[nb * 20 + kw + tg];
                unsigned bL1 = pBL[nb * 20 + kw + tg + 4];
                mma16816(acc[nt], aH, bH0, bH1);
                mma16816(acc[nt], aH, bL0, bL1);
                mma16816(acc[nt], aL, bH0, bH1);
            }
        }
        __syncthreads();
    }

    // --- epilogue: bias + relu; Q/K fp32, V bf16 ---
    const int gr0 = row0 + warp * 16 + g;
    const int gr1 = gr0 + 8;
    #pragma unroll
    for (int nt = 0; nt < 16; nt++) {
        int c = nt * 8 + tg * 2;
        float2 bb = *(const float2*)&bias[c];
        float v0 = fmaxf(acc[nt][0] + bb.x, 0.f);
        float v1 = fmaxf(acc[nt][1] + bb.y, 0.f);
        float v2 = fmaxf(acc[nt][2] + bb.x, 0.f);
        float v3 = fmaxf(acc[nt][3] + bb.y, 0.f);
        if (mat < 2) {
            float* out = g_QKV + (size_t)mat * NH;
            if (gr0 < N_NODES) *(float2*)&out[(size_t)gr0 * 128 + c] = make_float2(v0, v1);
            if (gr1 < N_NODES) *(float2*)&out[(size_t)gr1 * 128 + c] = make_float2(v2, v3);
        } else {
            if (gr0 < N_NODES) *(__nv_bfloat162*)&g_Vbf[(size_t)gr0 * 128 + c] = __floats2bfloat162_rn(v0, v1);
            if (gr1 < N_NODES) *(__nv_bfloat162*)&g_Vbf[(size_t)gr1 * 128 + c] = __floats2bfloat162_rn(v2, v3);
        }
    }
}

// ---------------- 7: gather-attention + finalize ----------------
__device__ __forceinline__ float edge_score(float4 k, float4 q) {
    float p = k.x * q.x + k.y * q.y + k.z * q.z + k.w * q.w;
    p += __shfl_xor_sync(0xffffffffu, p, 1);
    p += __shfl_xor_sync(0xffffffffu, p, 2);
    return __expf(fminf(fmaxf(p * 0.25f, -10.f), 10.f));
}

__device__ __forceinline__ void acc_v(float4& acc, uint2 raw, float sc) {
    float2 f0 = __bfloat1622float2(*reinterpret_cast<__nv_bfloat162*>(&raw.x));
    float2 f1 = __bfloat1622float2(*reinterpret_cast<__nv_bfloat162*>(&raw.y));
    acc.x += f0.x * sc; acc.y += f0.y * sc; acc.z += f1.x * sc; acc.w += f1.y * sc;
}

__global__ __launch_bounds__(256) void attn_gather(float* __restrict__ out) {
    int node = (blockIdx.x * blockDim.x + threadIdx.x) >> 5;
    int lane = threadIdx.x & 31;
    if (node >= N_NODES) return;
    int beg = g_rowptr[node], end = g_rowptr[node + 1];

    const float4* Q4 = (const float4*)g_QKV;
    const float4* K4 = (const float4*)(g_QKV + NH);
    const uint2* V2 = (const uint2*)g_Vbf;   // 8B = 4 bf16 feats per lane

    float4 q = Q4[(size_t)node * 32 + lane];
    float4 acc = make_float4(0.f, 0.f, 0.f, 0.f);
    float z = 0.f;

    int j = beg;
    for (; j + 4 <= end; j += 4) {
        int s0 = g_srt_src[j], s1 = g_srt_src[j + 1], s2 = g_srt_src[j + 2], s3 = g_srt_src[j + 3];
        float4 k0 = K4[(size_t)s0 * 32 + lane];
        float4 k1 = K4[(size_t)s1 * 32 + lane];
        float4 k2 = K4[(size_t)s2 * 32 + lane];
        float4 k3 = K4[(size_t)s3 * 32 + lane];
        uint2 v0 = V2[(size_t)s0 * 32 + lane];
        uint2 v1 = V2[(size_t)s1 * 32 + lane];
        uint2 v2 = V2[(size_t)s2 * 32 + lane];
        uint2 v3 = V2[(size_t)s3 * 32 + lane];
        float sc0 = edge_score(k0, q);
        float sc1 = edge_score(k1, q);
        float sc2 = edge_score(k2, q);
        float sc3 = edge_score(k3, q);
        acc_v(acc, v0, sc0); acc_v(acc, v1, sc1);
        acc_v(acc, v2, sc2); acc_v(acc, v3, sc3);
        z += (sc0 + sc1) + (sc2 + sc3);
    }
    for (; j < end; j++) {
        int s = g_srt_src[j];
        float4 k = K4[(size_t)s * 32 + lane];
        uint2 v = V2[(size_t)s * 32 + lane];
        float sc = edge_score(k, q);
        acc_v(acc, v, sc);
        z += sc;
    }

    float inv = 1.f / (z + 1e-6f);
    acc.x *= inv; acc.y *= inv; acc.z *= inv; acc.w *= inv;
    *(float4*)&out[(size_t)node * 128 + (lane << 2)] = acc;
}

// ---------------- launcher ----------------
extern "C" void kernel_launch(void* const* d_in, const int* in_sizes, int n_in,
                              void* d_out, int out_size) {
    const float* h  = (const float*)d_in[0];
    const float* Wq = (const float*)d_in[1];
    const float* bq = (const float*)d_in[2];
    const float* Wk = (const float*)d_in[3];
    const float* bk = (const float*)d_in[4];
    const float* Wv = (const float*)d_in[5];
    const float* bv = (const float*)d_in[6];
    const int*  src = (const int*)d_in[7];
    const int*  dst = (const int*)d_in[8];
    const int E = in_sizes[7];
    float* out = (float*)d_out;

    zero_cnt<<<(N_NODES + 255) / 256, 256>>>();
    degree_kernel<<<(E + 255) / 256, 256>>>(src, dst, E);
    scan_local<<<NCHUNK, 1024>>>();
    scan_chunks<<<1, 64>>>();
    finalize_csr<<<(N_NODES + 255) / 256, 256>>>();
    bucket_kernel<<<(E + 255) / 256, 256>>>(src, dst, E);
    prep_w<<<(3 * 128 * 128 + 255) / 256, 256>>>(Wq, Wk, Wv);

    int nwblocks = (N_NODES * 32 + 255) / 256;
    agg_gather<<<nwblocks, 256>>>(h);

    dim3 gg((N_NODES + 127) / 128, 3);
    gemm_qkv_mma<<<gg, 256>>>(bq, bk, bv);

    attn_gather<<<nwblocks, 256>>>(out);
}

// round 8
// speedup vs baseline: 2.2552x; 1.0287x over previous
#include <cuda_runtime.h>
#include <cuda_bf16.h>
#include <cuda_fp16.h>
#include <math.h>

#define N_NODES 50000
#define HIDDEN  128
#define HEADS   8
#define NH      (N_NODES * HIDDEN)
#define E_MAX   1600000
#define NCHUNK  ((N_NODES + 1023) / 1024)   // 49

// ---------------- scratch (device globals: allocation-free rule) ----------------
__device__ int   g_cnt_out[N_NODES];
__device__ int   g_cnt_in[N_NODES];
__device__ int   g_rowptr[N_NODES + 1];
__device__ int   g_cur[N_NODES];
__device__ int   g_srt_src[E_MAX];
__device__ int   g_chunk[64];
__device__ float g_norm_out[N_NODES];
__device__ float g_norm_in[N_NODES];
__device__ float g_agg[NH];                     // 25.6 MB (norm_in folded in)
__device__ float g_Qf[NH];                      // Q fp32 (25.6 MB)
__device__ __half g_Kh[NH];                     // K fp16 (12.8 MB)
__device__ __half g_Vh[NH];                     // V fp16 (12.8 MB)
__device__ __nv_bfloat16 g_Wt_hi[3][128 * 128]; // W^T split-bf16 high parts
__device__ __nv_bfloat16 g_Wt_lo[3][128 * 128]; // W^T split-bf16 low parts

// ---------------- 0: fused setup: zero counters + W -> transposed split-bf16 ----------------
__global__ void setup_kernel(const float* __restrict__ Wq, const float* __restrict__ Wk,
                             const float* __restrict__ Wv) {
    int t = blockIdx.x * 256 + threadIdx.x;
    if (t < N_NODES) { g_cnt_out[t] = 0; g_cnt_in[t] = 0; }
    if (t < 3 * 128 * 128) {
        int mat = t >> 14, rem = t & 16383;
        int n = rem >> 7, k = rem & 127;
        const float* W = (mat == 0) ? Wq : (mat == 1) ? Wk : Wv;
        float x = W[k * 128 + n];
        __nv_bfloat16 h = __float2bfloat16(x);
        g_Wt_hi[mat][n * 128 + k] = h;
        g_Wt_lo[mat][n * 128 + k] = __float2bfloat16(x - __bfloat162float(h));
    }
}

// ---------------- 1: degree histograms ----------------
__global__ void degree_kernel(const int* __restrict__ src, const int* __restrict__ dst, int E) {
    int e = blockIdx.x * blockDim.x + threadIdx.x;
    if (e < E) {
        atomicAdd(&g_cnt_out[src[e]], 1);
        atomicAdd(&g_cnt_in[dst[e]], 1);
    }
}

// ---------------- 2a: per-1024-chunk inclusive scan of in-degrees ----------------
__global__ void scan_local() {
    __shared__ int wsum[32];
    const int tid = threadIdx.x, lane = tid & 31, wid = tid >> 5;
    int i = blockIdx.x * 1024 + tid;
    int x = (i < N_NODES) ? g_cnt_in[i] : 0;
    #pragma unroll
    for (int o = 1; o < 32; o <<= 1) {
        int t = __shfl_up_sync(0xffffffffu, x, o);
        if (lane >= o) x += t;
    }
    if (lane == 31) wsum[wid] = x;
    __syncthreads();
    if (wid == 0) {
        int w = wsum[lane];
        #pragma unroll
        for (int o = 1; o < 32; o <<= 1) {
            int t = __shfl_up_sync(0xffffffffu, w, o);
            if (lane >= o) w += t;
        }
        wsum[lane] = w;
    }
    __syncthreads();
    int incl = x + (wid > 0 ? wsum[wid - 1] : 0);
    if (i < N_NODES) g_rowptr[i + 1] = incl;
    if (tid == 1023) g_chunk[blockIdx.x] = incl;
}

// ---------------- 2b: finalize rowptr + cursors + norms (chunk scan inlined per-block) ----------------
__global__ void finalize_csr() {
    __shared__ int pref[64];
    const int tid = threadIdx.x;
    if (tid < 64) pref[tid] = (tid < NCHUNK) ? g_chunk[tid] : 0;
    __syncthreads();
    #pragma unroll
    for (int off = 1; off < 64; off <<= 1) {
        int v = 0;
        if (tid < 64 && tid >= off) v = pref[tid - off];
        __syncthreads();
        if (tid < 64) pref[tid] += v;
        __syncthreads();
    }
    int i = blockIdx.x * blockDim.x + tid;
    if (i < N_NODES) {
        int c = i >> 10;
        int inc = g_rowptr[i + 1] + ((c > 0) ? pref[c - 1] : 0);
        g_rowptr[i + 1] = inc;
        int cin = g_cnt_in[i];
        g_cur[i] = inc - cin;
        g_norm_in[i]  = rsqrtf(fmaxf((float)cin, 1.f));
        g_norm_out[i] = rsqrtf(fmaxf((float)g_cnt_out[i], 1.f));
        if (i == 0) g_rowptr[0] = 0;
    }
}

// ---------------- 3: counting-sort bucket fill ----------------
__global__ void bucket_kernel(const int* __restrict__ src, const int* __restrict__ dst, int E) {
    int e = blockIdx.x * blockDim.x + threadIdx.x;
    if (e < E) {
        int p = atomicAdd(&g_cur[dst[e]], 1);
        g_srt_src[p] = src[e];
    }
}

// ---------------- 4: gather-aggregate ----------------
__global__ __launch_bounds__(256) void agg_gather(const float* __restrict__ h) {
    int node = (blockIdx.x * blockDim.x + threadIdx.x) >> 5;
    int lane = threadIdx.x & 31;
    if (node >= N_NODES) return;
    int beg = g_rowptr[node], end = g_rowptr[node + 1];
    const float4* h4 = (const float4*)h;
    float4 acc = make_float4(0.f, 0.f, 0.f, 0.f);
    int j = beg;
    for (; j + 4 <= end; j += 4) {
        int s0 = g_srt_src[j], s1 = g_srt_src[j + 1], s2 = g_srt_src[j + 2], s3 = g_srt_src[j + 3];
        float n0 = g_norm_out[s0], n1 = g_norm_out[s1], n2 = g_norm_out[s2], n3 = g_norm_out[s3];
        float4 a = h4[(size_t)s0 * 32 + lane];
        float4 b = h4[(size_t)s1 * 32 + lane];
        float4 c = h4[(size_t)s2 * 32 + lane];
        float4 d = h4[(size_t)s3 * 32 + lane];
        acc.x += a.x * n0 + b.x * n1 + c.x * n2 + d.x * n3;
        acc.y += a.y * n0 + b.y * n1 + c.y * n2 + d.y * n3;
        acc.z += a.z * n0 + b.z * n1 + c.z * n2 + d.z * n3;
        acc.w += a.w * n0 + b.w * n1 + c.w * n2 + d.w * n3;
    }
    for (; j < end; j++) {
        int s = g_srt_src[j];
        float n = g_norm_out[s];
        float4 a = h4[(size_t)s * 32 + lane];
        acc.x += a.x * n; acc.y += a.y * n; acc.z += a.z * n; acc.w += a.w * n;
    }
    float ni = g_norm_in[node];
    acc.x *= ni; acc.y *= ni; acc.z *= ni; acc.w *= ni;
    *(float4*)&g_agg[(size_t)node * 128 + (lane << 2)] = acc;
}

// ---------------- 5: QKV GEMM via split-bf16 tensor cores ----------------
__device__ __forceinline__ void mma16816(float* c, const unsigned* a, unsigned b0, unsigned b1) {
    asm volatile(
        "mma.sync.aligned.m16n8k16.row.col.f32.bf16.bf16.f32 "
        "{%0,%1,%2,%3}, {%4,%5,%6,%7}, {%8,%9}, {%0,%1,%2,%3};\n"
        : "+f"(c[0]), "+f"(c[1]), "+f"(c[2]), "+f"(c[3])
        : "r"(a[0]), "r"(a[1]), "r"(a[2]), "r"(a[3]), "r"(b0), "r"(b1));
}

// M-tile 128 x N 128, K streamed in 32-chunks. 8 warps, warp w owns rows [16w,16w+16).
__global__ __launch_bounds__(256, 2) void gemm_qkv_mma(
    const float* __restrict__ bq, const float* __restrict__ bk, const float* __restrict__ bv)
{
    const int mat = blockIdx.y;
    const float* bias = (mat == 0) ? bq : (mat == 1) ? bk : bv;
    const __nv_bfloat16* WtH = g_Wt_hi[mat];
    const __nv_bfloat16* WtL = g_Wt_lo[mat];

    // stride 40 bf16 (20 words): conflict-free frag loads
    __shared__ __nv_bfloat16 sA_hi[128 * 40];
    __shared__ __nv_bfloat16 sA_lo[128 * 40];
    __shared__ __nv_bfloat16 sB_hi[128 * 40];
    __shared__ __nv_bfloat16 sB_lo[128 * 40];

    const int tid = threadIdx.x;
    const int warp = tid >> 5, lane = tid & 31;
    const int g = lane >> 2, tg = lane & 3;
    const int row0 = blockIdx.x * 128;

    float acc[16][4];
    #pragma unroll
    for (int i = 0; i < 16; i++)
        #pragma unroll
        for (int j = 0; j < 4; j++) acc[i][j] = 0.f;

    const int r = tid >> 1;           // 0..127 (A row / B n-row)
    const int hh = tid & 1;           // half: 16 elems each

    for (int k0 = 0; k0 < 128; k0 += 32) {
        // --- load + split A tile [128 rows x 32 k] ---
        float xs[16];
        int arow = row0 + r;
        if (arow < N_NODES) {
            const float4* p = (const float4*)(g_agg + (size_t)arow * 128 + k0 + hh * 16);
            float4 a = p[0], b = p[1], c = p[2], d = p[3];
            xs[0]=a.x; xs[1]=a.y; xs[2]=a.z; xs[3]=a.w;
            xs[4]=b.x; xs[5]=b.y; xs[6]=b.z; xs[7]=b.w;
            xs[8]=c.x; xs[9]=c.y; xs[10]=c.z; xs[11]=c.w;
            xs[12]=d.x; xs[13]=d.y; xs[14]=d.z; xs[15]=d.w;
        } else {
            #pragma unroll
            for (int i = 0; i < 16; i++) xs[i] = 0.f;
        }
        __align__(16) __nv_bfloat16 hi[16], lo[16];
        #pragma unroll
        for (int i = 0; i < 16; i++) {
            hi[i] = __float2bfloat16(xs[i]);
            lo[i] = __float2bfloat16(xs[i] - __bfloat162float(hi[i]));
        }
        *(int4*)&sA_hi[r * 40 + hh * 16]     = ((int4*)hi)[0];
        *(int4*)&sA_hi[r * 40 + hh * 16 + 8] = ((int4*)hi)[1];
        *(int4*)&sA_lo[r * 40 + hh * 16]     = ((int4*)lo)[0];
        *(int4*)&sA_lo[r * 40 + hh * 16 + 8] = ((int4*)lo)[1];

        // --- load pre-split Wt tile [128 n x 32 k] ---
        const int4* srcH = (const int4*)(WtH + r * 128 + k0 + hh * 16);
        const int4* srcL = (const int4*)(WtL + r * 128 + k0 + hh * 16);
        *(int4*)&sB_hi[r * 40 + hh * 16]     = srcH[0];
        *(int4*)&sB_hi[r * 40 + hh * 16 + 8] = srcH[1];
        *(int4*)&sB_lo[r * 40 + hh * 16]     = srcL[0];
        *(int4*)&sB_lo[r * 40 + hh * 16 + 8] = srcL[1];
        __syncthreads();

        const unsigned* pAH = (const unsigned*)sA_hi;
        const unsigned* pAL = (const unsigned*)sA_lo;
        const unsigned* pBH = (const unsigned*)sB_hi;
        const unsigned* pBL = (const unsigned*)sB_lo;
        const int ra = warp * 16 + g;

        #pragma unroll
        for (int kw = 0; kw <= 8; kw += 8) {   // two k16 sub-steps (word offset 0, 8)
            unsigned aH[4], aL[4];
            aH[0] = pAH[ra * 20 + kw + tg];
            aH[1] = pAH[(ra + 8) * 20 + kw + tg];
            aH[2] = pAH[ra * 20 + kw + tg + 4];
            aH[3] = pAH[(ra + 8) * 20 + kw + tg + 4];
            aL[0] = pAL[ra * 20 + kw + tg];
            aL[1] = pAL[(ra + 8) * 20 + kw + tg];
            aL[2] = pAL[ra * 20 + kw + tg + 4];
            aL[3] = pAL[(ra + 8) * 20 + kw + tg + 4];
            #pragma unroll
            for (int nt = 0; nt < 16; nt++) {
                int nb = nt * 8 + g;
                unsigned bH0 = pBH[nb * 20 + kw + tg];
                unsigned bH1 = pBH[nb * 20 + kw + tg + 4];
                unsigned bL0 = pBL[nb * 20 + kw + tg];
                unsigned bL1 = pBL[nb * 20 + kw + tg + 4];
                mma16816(acc[nt], aH, bH0, bH1);
                mma16816(acc[nt], aH, bL0, bL1);
                mma16816(acc[nt], aL, bH0, bH1);
            }
        }
        __syncthreads();
    }

    // --- epilogue: bias + relu; Q fp32, K/V fp16 ---
    const int gr0 = row0 + warp * 16 + g;
    const int gr1 = gr0 + 8;
    #pragma unroll
    for (int nt = 0; nt < 16; nt++) {
        int c = nt * 8 + tg * 2;
        float2 bb = *(const float2*)&bias[c];
        float v0 = fmaxf(acc[nt][0] + bb.x, 0.f);
        float v1 = fmaxf(acc[nt][1] + bb.y, 0.f);
        float v2 = fmaxf(acc[nt][2] + bb.x, 0.f);
        float v3 = fmaxf(acc[nt][3] + bb.y, 0.f);
        if (mat == 0) {
            if (gr0 < N_NODES) *(float2*)&g_Qf[(size_t)gr0 * 128 + c] = make_float2(v0, v1);
            if (gr1 < N_NODES) *(float2*)&g_Qf[(size_t)gr1 * 128 + c] = make_float2(v2, v3);
        } else {
            __half* dstp = (mat == 1) ? g_Kh : g_Vh;
            if (gr0 < N_NODES) *(__half2*)&dstp[(size_t)gr0 * 128 + c] = __floats2half2_rn(v0, v1);
            if (gr1 < N_NODES) *(__half2*)&dstp[(size_t)gr1 * 128 + c] = __floats2half2_rn(v2, v3);
        }
    }
}

// ---------------- 6: gather-attention + finalize ----------------
// per lane: 4 feats. K/V rows are fp16 -> uint2 (8B) per lane.
__device__ __forceinline__ float edge_score_h(uint2 kraw, float4 q) {
    float2 k01 = __half22float2(*reinterpret_cast<__half2*>(&kraw.x));
    float2 k23 = __half22float2(*reinterpret_cast<__half2*>(&kraw.y));
    float p = k01.x * q.x + k01.y * q.y + k23.x * q.z + k23.y * q.w;
    p += __shfl_xor_sync(0xffffffffu, p, 1);
    p += __shfl_xor_sync(0xffffffffu, p, 2);
    return __expf(fminf(fmaxf(p * 0.25f, -10.f), 10.f));
}

__device__ __forceinline__ void acc_vh(float4& acc, uint2 raw, float sc) {
    float2 f0 = __half22float2(*reinterpret_cast<__half2*>(&raw.x));
    float2 f1 = __half22float2(*reinterpret_cast<__half2*>(&raw.y));
    acc.x += f0.x * sc; acc.y += f0.y * sc; acc.z += f1.x * sc; acc.w += f1.y * sc;
}

__global__ __launch_bounds__(256) void attn_gather(float* __restrict__ out) {
    int node = (blockIdx.x * blockDim.x + threadIdx.x) >> 5;
    int lane = threadIdx.x & 31;
    if (node >= N_NODES) return;
    int beg = g_rowptr[node], end = g_rowptr[node + 1];

    const float4* Q4 = (const float4*)g_Qf;
    const uint2* K2 = (const uint2*)g_Kh;
    const uint2* V2 = (const uint2*)g_Vh;

    float4 q = Q4[(size_t)node * 32 + lane];
    float4 acc = make_float4(0.f, 0.f, 0.f, 0.f);
    float z = 0.f;

    int j = beg;
    for (; j + 4 <= end; j += 4) {
        int s0 = g_srt_src[j], s1 = g_srt_src[j + 1], s2 = g_srt_src[j + 2], s3 = g_srt_src[j + 3];
        uint2 k0 = K2[(size_t)s0 * 32 + lane];
        uint2 k1 = K2[(size_t)s1 * 32 + lane];
        uint2 k2 = K2[(size_t)s2 * 32 + lane];
        uint2 k3 = K2[(size_t)s3 * 32 + lane];
        uint2 v0 = V2[(size_t)s0 * 32 + lane];
        uint2 v1 = V2[(size_t)s1 * 32 + lane];
        uint2 v2 = V2[(size_t)s2 * 32 + lane];
        uint2 v3 = V2[(size_t)s3 * 32 + lane];
        float sc0 = edge_score_h(k0, q);
        float sc1 = edge_score_h(k1, q);
        float sc2 = edge_score_h(k2, q);
        float sc3 = edge_score_h(k3, q);
        acc_vh(acc, v0, sc0); acc_vh(acc, v1, sc1);
        acc_vh(acc, v2, sc2); acc_vh(acc, v3, sc3);
        z += (sc0 + sc1) + (sc2 + sc3);
    }
    for (; j < end; j++) {
        int s = g_srt_src[j];
        uint2 k = K2[(size_t)s * 32 + lane];
        uint2 v = V2[(size_t)s * 32 + lane];
        float sc = edge_score_h(k, q);
        acc_vh(acc, v, sc);
        z += sc;
    }

    float inv = 1.f / (z + 1e-6f);
    acc.x *= inv; acc.y *= inv; acc.z *= inv; acc.w *= inv;
    *(float4*)&out[(size_t)node * 128 + (lane << 2)] = acc;
}

// ---------------- launcher ----------------
extern "C" void kernel_launch(void* const* d_in, const int* in_sizes, int n_in,
                              void* d_out, int out_size) {
    const float* h  = (const float*)d_in[0];
    const float* Wq = (const float*)d_in[1];
    const float* bq = (const float*)d_in[2];
    const float* Wk = (const float*)d_in[3];
    const float* bk = (const float*)d_in[4];
    const float* Wv = (const float*)d_in[5];
    const float* bv = (const float*)d_in[6];
    const int*  src = (const int*)d_in[7];
    const int*  dst = (const int*)d_in[8];
    const int E = in_sizes[7];
    float* out = (float*)d_out;

    setup_kernel<<<(N_NODES + 255) / 256, 256>>>(Wq, Wk, Wv);
    degree_kernel<<<(E + 255) / 256, 256>>>(src, dst, E);
    scan_local<<<NCHUNK, 1024>>>();
    finalize_csr<<<(N_NODES + 255) / 256, 256>>>();
    bucket_kernel<<<(E + 255) / 256, 256>>>(src, dst, E);

    int nwblocks = (N_NODES * 32 + 255) / 256;
    agg_gather<<<nwblocks, 256>>>(h);

    dim3 gg((N_NODES + 127) / 128, 3);
    gemm_qkv_mma<<<gg, 256>>>(bq, bk, bv);

    attn_gather<<<nwblocks, 256>>>(out);
}

// round 11
// speedup vs baseline: 2.3879x; 1.0588x over previous
#include <cuda_runtime.h>
#include <cuda_bf16.h>
#include <cuda_fp16.h>
#include <math.h>

#define N_NODES 50000
#define HIDDEN  128
#define HEADS   8
#define NH      (N_NODES * HIDDEN)
#define E_MAX   1600000
#define NCHUNK  ((N_NODES + 1023) / 1024)   // 49

// ---------------- scratch (device globals: allocation-free rule) ----------------
__device__ int   g_cnt_out[N_NODES];
__device__ int   g_cnt_in[N_NODES];
__device__ int   g_rowptr[N_NODES + 1];
__device__ int   g_cur[N_NODES];
__device__ int   g_srt_src[E_MAX];
__device__ int   g_chunk[64];
__device__ float g_norm_out[N_NODES];
__device__ float g_norm_in[N_NODES];
__device__ __half g_hh[NH];                     // h * norm_out, fp16 (12.8 MB)
__device__ float g_agg[NH];                     // 25.6 MB (norms folded in)
__device__ float g_Qf[NH];                      // Q fp32 (25.6 MB)
__device__ __half g_KVh[2 * NH];                // K|V interleaved per lane: 8 halfs = 4K + 4V (25.6 MB)
__device__ __nv_bfloat16 g_Wt_hi[3][128 * 128]; // W^T split-bf16 high parts
__device__ __nv_bfloat16 g_Wt_lo[3][128 * 128]; // W^T split-bf16 low parts

// ---------------- 0: fused setup: zero counters + W -> transposed split-bf16 ----------------
__global__ void setup_kernel(const float* __restrict__ Wq, const float* __restrict__ Wk,
                             const float* __restrict__ Wv) {
    int t = blockIdx.x * 256 + threadIdx.x;
    if (t < N_NODES) { g_cnt_out[t] = 0; g_cnt_in[t] = 0; }
    if (t < 3 * 128 * 128) {
        int mat = t >> 14, rem = t & 16383;
        int n = rem >> 7, k = rem & 127;
        const float* W = (mat == 0) ? Wq : (mat == 1) ? Wk : Wv;
        float x = W[k * 128 + n];
        __nv_bfloat16 h = __float2bfloat16(x);
        g_Wt_hi[mat][n * 128 + k] = h;
        g_Wt_lo[mat][n * 128 + k] = __float2bfloat16(x - __bfloat162float(h));
    }
}

// ---------------- 1: degree histograms ----------------
__global__ void degree_kernel(const int* __restrict__ src, const int* __restrict__ dst, int E) {
    int e = blockIdx.x * blockDim.x + threadIdx.x;
    if (e < E) {
        atomicAdd(&g_cnt_out[src[e]], 1);
        atomicAdd(&g_cnt_in[dst[e]], 1);
    }
}

// ---------------- 2a: per-1024-chunk inclusive scan of in-degrees ----------------
__global__ void scan_local() {
    __shared__ int wsum[32];
    const int tid = threadIdx.x, lane = tid & 31, wid = tid >> 5;
    int i = blockIdx.x * 1024 + tid;
    int x = (i < N_NODES) ? g_cnt_in[i] : 0;
    #pragma unroll
    for (int o = 1; o < 32; o <<= 1) {
        int t = __shfl_up_sync(0xffffffffu, x, o);
        if (lane >= o) x += t;
    }
    if (lane == 31) wsum[wid] = x;
    __syncthreads();
    if (wid == 0) {
        int w = wsum[lane];
        #pragma unroll
        for (int o = 1; o < 32; o <<= 1) {
            int t = __shfl_up_sync(0xffffffffu, w, o);
            if (lane >= o) w += t;
        }
        wsum[lane] = w;
    }
    __syncthreads();
    int incl = x + (wid > 0 ? wsum[wid - 1] : 0);
    if (i < N_NODES) g_rowptr[i + 1] = incl;
    if (tid == 1023) g_chunk[blockIdx.x] = incl;
}

// ---------------- 2b: finalize rowptr + cursors + norms (chunk scan inlined per-block) ----------------
__global__ void finalize_csr() {
    __shared__ int pref[64];
    const int tid = threadIdx.x;
    if (tid < 64) pref[tid] = (tid < NCHUNK) ? g_chunk[tid] : 0;
    __syncthreads();
    #pragma unroll
    for (int off = 1; off < 64; off <<= 1) {
        int v = 0;
        if (tid < 64 && tid >= off) v = pref[tid - off];
        __syncthreads();
        if (tid < 64) pref[tid] += v;
        __syncthreads();
    }
    int i = blockIdx.x * blockDim.x + tid;
    if (i < N_NODES) {
        int c = i >> 10;
        int inc = g_rowptr[i + 1] + ((c > 0) ? pref[c - 1] : 0);
        g_rowptr[i + 1] = inc;
        int cin = g_cnt_in[i];
        g_cur[i] = inc - cin;
        g_norm_in[i]  = rsqrtf(fmaxf((float)cin, 1.f));
        g_norm_out[i] = rsqrtf(fmaxf((float)g_cnt_out[i], 1.f));
        if (i == 0) g_rowptr[0] = 0;
    }
}

// ---------------- 3: counting-sort bucket fill ----------------
__global__ void bucket_kernel(const int* __restrict__ src, const int* __restrict__ dst, int E) {
    int e = blockIdx.x * blockDim.x + threadIdx.x;
    if (e < E) {
        int p = atomicAdd(&g_cur[dst[e]], 1);
        g_srt_src[p] = src[e];
    }
}

// ---------------- 3b: prescale h*norm_out -> fp16 ----------------
__global__ void prescale_h(const float* __restrict__ h) {
    int i = blockIdx.x * 256 + threadIdx.x;   // one uint2 (4 halfs) per thread
    if (i < NH / 4) {
        int node = i >> 5;
        float no = g_norm_out[node];
        float4 a = ((const float4*)h)[i];
        __half2 h0 = __floats2half2_rn(a.x * no, a.y * no);
        __half2 h1 = __floats2half2_rn(a.z * no, a.w * no);
        uint2 out;
        out.x = *reinterpret_cast<unsigned*>(&h0);
        out.y = *reinterpret_cast<unsigned*>(&h1);
        ((uint2*)g_hh)[i] = out;
    }
}

// ---------------- 4: gather-aggregate (fp16 prescaled h) ----------------
__device__ __forceinline__ void acc_h2(float4& acc, uint2 raw) {
    float2 f0 = __half22float2(*reinterpret_cast<__half2*>(&raw.x));
    float2 f1 = __half22float2(*reinterpret_cast<__half2*>(&raw.y));
    acc.x += f0.x; acc.y += f0.y; acc.z += f1.x; acc.w += f1.y;
}

__global__ __launch_bounds__(256) void agg_gather() {
    int node = (blockIdx.x * blockDim.x + threadIdx.x) >> 5;
    int lane = threadIdx.x & 31;
    if (node >= N_NODES) return;
    int beg = g_rowptr[node], end = g_rowptr[node + 1];
    const uint2* h2 = (const uint2*)g_hh;
    float4 acc = make_float4(0.f, 0.f, 0.f, 0.f);
    int j = beg;
    for (; j + 4 <= end; j += 4) {
        int s0 = g_srt_src[j], s1 = g_srt_src[j + 1], s2 = g_srt_src[j + 2], s3 = g_srt_src[j + 3];
        uint2 a = h2[(size_t)s0 * 32 + lane];
        uint2 b = h2[(size_t)s1 * 32 + lane];
        uint2 c = h2[(size_t)s2 * 32 + lane];
        uint2 d = h2[(size_t)s3 * 32 + lane];
        acc_h2(acc, a); acc_h2(acc, b); acc_h2(acc, c); acc_h2(acc, d);
    }
    for (; j < end; j++) {
        int s = g_srt_src[j];
        acc_h2(acc, h2[(size_t)s * 32 + lane]);
    }
    float ni = g_norm_in[node];
    acc.x *= ni; acc.y *= ni; acc.z *= ni; acc.w *= ni;
    *(float4*)&g_agg[(size_t)node * 128 + (lane << 2)] = acc;
}

// ---------------- 5: QKV GEMM via split-bf16 tensor cores ----------------
__device__ __forceinline__ void mma16816(float* c, const unsigned* a, unsigned b0, unsigned b1) {
    asm volatile(
        "mma.sync.aligned.m16n8k16.row.col.f32.bf16.bf16.f32 "
        "{%0,%1,%2,%3}, {%4,%5,%6,%7}, {%8,%9}, {%0,%1,%2,%3};\n"
        : "+f"(c[0]), "+f"(c[1]), "+f"(c[2]), "+f"(c[3])
        : "r"(a[0]), "r"(a[1]), "r"(a[2]), "r"(a[3]), "r"(b0), "r"(b1));
}

// M-tile 128 x N 128, K streamed in 32-chunks. 8 warps, warp w owns rows [16w,16w+16).
__global__ __launch_bounds__(256, 2) void gemm_qkv_mma(
    const float* __restrict__ bq, const float* __restrict__ bk, const float* __restrict__ bv)
{
    const int mat = blockIdx.y;
    const float* bias = (mat == 0) ? bq : (mat == 1) ? bk : bv;
    const __nv_bfloat16* WtH = g_Wt_hi[mat];
    const __nv_bfloat16* WtL = g_Wt_lo[mat];

    // stride 40 bf16 (20 words): conflict-free frag loads
    __shared__ __nv_bfloat16 sA_hi[128 * 40];
    __shared__ __nv_bfloat16 sA_lo[128 * 40];
    __shared__ __nv_bfloat16 sB_hi[128 * 40];
    __shared__ __nv_bfloat16 sB_lo[128 * 40];

    const int tid = threadIdx.x;
    const int warp = tid >> 5, lane = tid & 31;
    const int g = lane >> 2, tg = lane & 3;
    const int row0 = blockIdx.x * 128;

    float acc[16][4];
    #pragma unroll
    for (int i = 0; i < 16; i++)
        #pragma unroll
        for (int j = 0; j < 4; j++) acc[i][j] = 0.f;

    const int r = tid >> 1;           // 0..127 (A row / B n-row)
    const int hh = tid & 1;           // half: 16 elems each

    for (int k0 = 0; k0 < 128; k0 += 32) {
        // --- load + split A tile [128 rows x 32 k] ---
        float xs[16];
        int arow = row0 + r;
        if (arow < N_NODES) {
            const float4* p = (const float4*)(g_agg + (size_t)arow * 128 + k0 + hh * 16);
            float4 a = p[0], b = p[1], c = p[2], d = p[3];
            xs[0]=a.x; xs[1]=a.y; xs[2]=a.z; xs[3]=a.w;
            xs[4]=b.x; xs[5]=b.y; xs[6]=b.z; xs[7]=b.w;
            xs[8]=c.x; xs[9]=c.y; xs[10]=c.z; xs[11]=c.w;
            xs[12]=d.x; xs[13]=d.y; xs[14]=d.z; xs[15]=d.w;
        } else {
            #pragma unroll
            for (int i = 0; i < 16; i++) xs[i] = 0.f;
        }
        __align__(16) __nv_bfloat16 hi[16], lo[16];
        #pragma unroll
        for (int i = 0; i < 16; i++) {
            hi[i] = __float2bfloat16(xs[i]);
            lo[i] = __float2bfloat16(xs[i] - __bfloat162float(hi[i]));
        }
        *(int4*)&sA_hi[r * 40 + hh * 16]     = ((int4*)hi)[0];
        *(int4*)&sA_hi[r * 40 + hh * 16 + 8] = ((int4*)hi)[1];
        *(int4*)&sA_lo[r * 40 + hh * 16]     = ((int4*)lo)[0];
        *(int4*)&sA_lo[r * 40 + hh * 16 + 8] = ((int4*)lo)[1];

        // --- load pre-split Wt tile [128 n x 32 k] ---
        const int4* srcH = (const int4*)(WtH + r * 128 + k0 + hh * 16);
        const int4* srcL = (const int4*)(WtL + r * 128 + k0 + hh * 16);
        *(int4*)&sB_hi[r * 40 + hh * 16]     = srcH[0];
        *(int4*)&sB_hi[r * 40 + hh * 16 + 8] = srcH[1];
        *(int4*)&sB_lo[r * 40 + hh * 16]     = srcL[0];
        *(int4*)&sB_lo[r * 40 + hh * 16 + 8] = srcL[1];
        __syncthreads();

        const unsigned* pAH = (const unsigned*)sA_hi;
        const unsigned* pAL = (const unsigned*)sA_lo;
        const unsigned* pBH = (const unsigned*)sB_hi;
        const unsigned* pBL = (const unsigned*)sB_lo;
        const int ra = warp * 16 + g;

        #pragma unroll
        for (int kw = 0; kw <= 8; kw += 8) {   // two k16 sub-steps (word offset 0, 8)
            unsigned aH[4], aL[4];
            aH[0] = pAH[ra * 20 + kw + tg];
            aH[1] = pAH[(ra + 8) * 20 + kw + tg];
            aH[2] = pAH[ra * 20 + kw + tg + 4];
            aH[3] = pAH[(ra + 8) * 20 + kw + tg + 4];
            aL[0] = pAL[ra * 20 + kw + tg];
            aL[1] = pAL[(ra + 8) * 20 + kw + tg];
            aL[2] = pAL[ra * 20 + kw + tg + 4];
            aL[3] = pAL[(ra + 8) * 20 + kw + tg + 4];
            #pragma unroll
            for (int nt = 0; nt < 16; nt++) {
                int nb = nt * 8 + g;
                unsigned bH0 = pBH[nb * 20 + kw + tg];
                unsigned bH1 = pBH[nb * 20 + kw + tg + 4];
                unsigned bL0 = pBL[nb * 20 + kw + tg];
                unsigned bL1 = pBL[nb * 20 + kw + tg + 4];
                mma16816(acc[nt], aH, bH0, bH1);
                mma16816(acc[nt], aH, bL0, bL1);
                mma16816(acc[nt], aL, bH0, bH1);
            }
        }
        __syncthreads();
    }

    // --- epilogue: bias + relu; Q fp32; K/V fp16 interleaved per lane ---
    const int gr0 = row0 + warp * 16 + g;
    const int gr1 = gr0 + 8;
    #pragma unroll
    for (int nt = 0; nt < 16; nt++) {
        int c = nt * 8 + tg * 2;
        float2 bb = *(const float2*)&bias[c];
        float v0 = fmaxf(acc[nt][0] + bb.x, 0.f);
        float v1 = fmaxf(acc[nt][1] + bb.y, 0.f);
        float v2 = fmaxf(acc[nt][2] + bb.x, 0.f);
        float v3 = fmaxf(acc[nt][3] + bb.y, 0.f);
        if (mat == 0) {
            if (gr0 < N_NODES) *(float2*)&g_Qf[(size_t)gr0 * 128 + c] = make_float2(v0, v1);
            if (gr1 < N_NODES) *(float2*)&g_Qf[(size_t)gr1 * 128 + c] = make_float2(v2, v3);
        } else {
            // interleaved layout: node row = 32 lanes x 8 halfs [k0..k3, v0..v3]
            // feat c -> lane (c>>2), slot (c&3); K at slot, V at slot+4
            size_t off = ((size_t)(c >> 2) << 3) + (c & 3) + ((mat == 2) ? 4 : 0);
            if (gr0 < N_NODES) *(__half2*)&g_KVh[(size_t)gr0 * 256 + off] = __floats2half2_rn(v0, v1);
            if (gr1 < N_NODES) *(__half2*)&g_KVh[(size_t)gr1 * 256 + off] = __floats2half2_rn(v2, v3);
        }
    }
}

// ---------------- 6: gather-attention + finalize ----------------
// per lane: one uint4 = 4 K-feats + 4 V-feats (fp16)
__device__ __forceinline__ float edge_score_kv(uint4 kv, float4 q) {
    float2 k01 = __half22float2(*reinterpret_cast<__half2*>(&kv.x));
    float2 k23 = __half22float2(*reinterpret_cast<__half2*>(&kv.y));
    float p = k01.x * q.x + k01.y * q.y + k23.x * q.z + k23.y * q.w;
    p += __shfl_xor_sync(0xffffffffu, p, 1);
    p += __shfl_xor_sync(0xffffffffu, p, 2);
    return __expf(fminf(fmaxf(p * 0.25f, -10.f), 10.f));
}

__device__ __forceinline__ void acc_kv(float4& acc, uint4 kv, float sc) {
    float2 f0 = __half22float2(*reinterpret_cast<__half2*>(&kv.z));
    float2 f1 = __half22float2(*reinterpret_cast<__half2*>(&kv.w));
    acc.x += f0.x * sc; acc.y += f0.y * sc; acc.z += f1.x * sc; acc.w += f1.y * sc;
}

__global__ __launch_bounds__(256) void attn_gather(float* __restrict__ out) {
    int node = (blockIdx.x * blockDim.x + threadIdx.x) >> 5;
    int lane = threadIdx.x & 31;
    if (node >= N_NODES) return;
    int beg = g_rowptr[node], end = g_rowptr[node + 1];

    const float4* Q4 = (const float4*)g_Qf;
    const uint4* KV4 = (const uint4*)g_KVh;

    float4 q = Q4[(size_t)node * 32 + lane];
    float4 acc = make_float4(0.f, 0.f, 0.f, 0.f);
    float z = 0.f;

    int j = beg;
    for (; j + 4 <= end; j += 4) {
        int s0 = g_srt_src[j], s1 = g_srt_src[j + 1], s2 = g_srt_src[j + 2], s3 = g_srt_src[j + 3];
        uint4 kv0 = KV4[(size_t)s0 * 32 + lane];
        uint4 kv1 = KV4[(size_t)s1 * 32 + lane];
        uint4 kv2 = KV4[(size_t)s2 * 32 + lane];
        uint4 kv3 = KV4[(size_t)s3 * 32 + lane];
        float sc0 = edge_score_kv(kv0, q);
        float sc1 = edge_score_kv(kv1, q);
        float sc2 = edge_score_kv(kv2, q);
        float sc3 = edge_score_kv(kv3, q);
        acc_kv(acc, kv0, sc0); acc_kv(acc, kv1, sc1);
        acc_kv(acc, kv2, sc2); acc_kv(acc, kv3, sc3);
        z += (sc0 + sc1) + (sc2 + sc3);
    }
    for (; j < end; j++) {
        int s = g_srt_src[j];
        uint4 kv = KV4[(size_t)s * 32 + lane];
        float sc = edge_score_kv(kv, q);
        acc_kv(acc, kv, sc);
        z += sc;
    }

    float inv = 1.f / (z + 1e-6f);
    acc.x *= inv; acc.y *= inv; acc.z *= inv; acc.w *= inv;
    *(float4*)&out[(size_t)node * 128 + (lane << 2)] = acc;
}

// ---------------- launcher ----------------
extern "C" void kernel_launch(void* const* d_in, const int* in_sizes, int n_in,
                              void* d_out, int out_size) {
    const float* h  = (const float*)d_in[0];
    const float* Wq = (const float*)d_in[1];
    const float* bq = (const float*)d_in[2];
    const float* Wk = (const float*)d_in[3];
    const float* bk = (const float*)d_in[4];
    const float* Wv = (const float*)d_in[5];
    const float* bv = (const float*)d_in[6];
    const int*  src = (const int*)d_in[7];
    const int*  dst = (const int*)d_in[8];
    const int E = in_sizes[7];
    float* out = (float*)d_out;

    setup_kernel<<<(N_NODES + 255) / 256, 256>>>(Wq, Wk, Wv);
    degree_kernel<<<(E + 255) / 256, 256>>>(src, dst, E);
    scan_local<<<NCHUNK, 1024>>>();
    finalize_csr<<<(N_NODES + 255) / 256, 256>>>();
    bucket_kernel<<<(E + 255) / 256, 256>>>(src, dst, E);
    prescale_h<<<(NH / 4 + 255) / 256, 256>>>(h);

    int nwblocks = (N_NODES * 32 + 255) / 256;
    agg_gather<<<nwblocks, 256>>>();

    dim3 gg((N_NODES + 127) / 128, 3);
    gemm_qkv_mma<<<gg, 256>>>(bq, bk, bv);

    attn_gather<<<nwblocks, 256>>>(out);
}